// round 15
// baseline (speedup 1.0000x reference)
#include <cuda_runtime.h>

// WaveletDWTLayer: fused db4 DWT + 2x IDWT, one CTA per batch row.
// Outputs concatenated: cA [B,1,2051] | cDs [B,2,1,4096] | R [B,1,1,8186]
// R2 champion, byte-for-byte (best recorded: 86.3us bench / 81.9us kernel).
// Reproducibility run in a verified good environment regime.

namespace {
constexpr int L    = 4096;        // signal length
constexpr int NC   = 2051;        // dwt coeff count = (L+7)/2
constexpr int EXT  = L + 13;      // symmetric-extended length (4109)
constexpr int RLEN = 2 * L - 6;   // final idwt output length (8186)

// REC_LO (used as analysis filter in the reference's conv)
__device__ constexpr float RLO[8] = {
     0.23037781330885523f,  0.7148465705525415f,   0.6308807679295904f,  -0.02798376941698385f,
    -0.18703481171888114f,  0.030841381835986965f, 0.032883011666982945f,-0.010597401784997278f};
// REC_HI[k] = (-1)^k * REC_LO[7-k]
__device__ constexpr float RHI[8] = {
    -0.010597401784997278f,-0.032883011666982945f, 0.030841381835986965f, 0.18703481171888114f,
    -0.02798376941698385f, -0.6308807679295904f,   0.7148465705525415f,  -0.23037781330885523f};
// DEC_LO[k] = REC_LO[7-k]
__device__ constexpr float DLO[8] = {
    -0.010597401784997278f, 0.032883011666982945f, 0.030841381835986965f,-0.18703481171888114f,
    -0.02798376941698385f,  0.6308807679295904f,   0.7148465705525415f,   0.23037781330885523f};
// DEC_HI[k] = REC_HI[7-k]
__device__ constexpr float DHI[8] = {
    -0.23037781330885523f,  0.7148465705525415f,  -0.6308807679295904f,  -0.02798376941698385f,
     0.18703481171888114f,  0.030841381835986965f,-0.032883011666982945f,-0.010597401784997278f};
} // namespace

__global__ __launch_bounds__(256)
void wavelet_fused_kernel(const float* __restrict__ x1,
                          const float* __restrict__ x2,
                          float* __restrict__ out, int B)
{
    __shared__ float s_x[EXT + 3];   // phase 1-2: ext(x1); phase 3+: x2 row (first L)
    __shared__ float s_cD[NC + 1];
    __shared__ float s_a[L];

    const int b = blockIdx.x;
    const int t = threadIdx.x;

    const float* __restrict__ x1row = x1 + (size_t)b * L;
    const float* __restrict__ x2row = x2 + (size_t)b * L;

    float* __restrict__ outA = out + (size_t)b * NC;
    float* __restrict__ outD = out + (size_t)B * NC + (size_t)b * (2 * L);
    float* __restrict__ outR = out + (size_t)B * NC + (size_t)B * (2 * L)
                                   + (size_t)b * RLEN;

    // ---- Phase 1: symmetric-extended x1 into smem ----
    // ext = [x5..x0 | x0..x_{L-1} | x_{L-1}..x_{L-7}]  (length L+13)
    for (int j = t; j < EXT; j += 256) {
        int src = (j < 6) ? (5 - j) : ((j <= L + 5) ? (j - 6) : (2 * L + 5 - j));
        s_x[j] = x1row[src];
    }
    __syncthreads();

    // ---- Phase 2: DWT (stride-2, 8-tap, cross-correlation) ----
    // cA -> gmem; cD -> smem and gmem (channel 1 of cDs); FILLER tail.
    for (int i = t; i < NC; i += 256) {
        float lo = 0.f, hi = 0.f;
#pragma unroll
        for (int k = 0; k < 8; k++) {
            float v = s_x[2 * i + k];
            lo = fmaf(v, RLO[k], lo);
            hi = fmaf(v, RHI[k], hi);
        }
        outA[i]     = lo;
        s_cD[i]     = hi;
        outD[L + i] = hi;          // cDs channel 1
    }
    for (int i = NC + t; i < L; i += 256) outD[L + i] = 10.1f;  // FILLER
    __syncthreads();

    // ---- Phase 3: a = idwt(0, cD) -> s_a ; reload s_x with x2 ; copy x2 -> cDs ch 0 ----
    // For output i of idwt: m = i>>1; even i uses filter taps {1,3,5,7}, odd uses {0,2,4,6}.
    // Output length 2n-6 means no boundary clipping is ever required.
    for (int u = t; u < L / 2; u += 256) {
        float c0 = s_cD[u], c1 = s_cD[u + 1], c2 = s_cD[u + 2], c3 = s_cD[u + 3];
        float e = fmaf(c0, DHI[1], fmaf(c1, DHI[3], fmaf(c2, DHI[5], c3 * DHI[7])));
        float o = fmaf(c0, DHI[0], fmaf(c1, DHI[2], fmaf(c2, DHI[4], c3 * DHI[6])));
        s_a[2 * u]     = e;
        s_a[2 * u + 1] = o;
    }
    for (int i = t; i < L; i += 256) {  // s_x no longer read by anyone (synced above)
        float v = x2row[i];
        s_x[i]  = v;
        outD[i] = v;                    // cDs channel 0
    }
    __syncthreads();

    // ---- Phase 4: R = idwt(a, x2), paired outputs + float2 stores ----
    for (int u = t; u < RLEN / 2; u += 256) {
        float a0 = s_a[u], a1 = s_a[u + 1], a2 = s_a[u + 2], a3 = s_a[u + 3];
        float b0 = s_x[u], b1 = s_x[u + 1], b2 = s_x[u + 2], b3 = s_x[u + 3];

        float e = fmaf(a0, DLO[1], fmaf(a1, DLO[3], fmaf(a2, DLO[5], a3 * DLO[7])));
        e = fmaf(b0, DHI[1], fmaf(b1, DHI[3], fmaf(b2, DHI[5], fmaf(b3, DHI[7], e))));
        float o = fmaf(a0, DLO[0], fmaf(a1, DLO[2], fmaf(a2, DLO[4], a3 * DLO[6])));
        o = fmaf(b0, DHI[0], fmaf(b1, DHI[2], fmaf(b2, DHI[4], fmaf(b3, DHI[6], o))));

        *reinterpret_cast<float2*>(outR + 2 * u) = make_float2(e, o);
    }
}

extern "C" void kernel_launch(void* const* d_in, const int* in_sizes, int n_in,
                              void* d_out, int out_size) {
    const float* x1 = (const float*)d_in[0];   // [B,1,L]
    const float* x2 = (const float*)d_in[1];   // [B,1,1,L]
    // d_in[2] = x3 [B,1,1,1] is unused by the reference.
    int B = in_sizes[2];                       // x3 has exactly B elements
    wavelet_fused_kernel<<<B, 256>>>(x1, x2, (float*)d_out, B);
}

// round 16
// speedup vs baseline: 1.7654x; 1.7654x over previous
#include <cuda_runtime.h>

// WaveletDWTLayer: fused db4 DWT + 2x IDWT, one CTA per batch row.
// Outputs concatenated: cA [B,1,2051] | cDs [B,2,1,4096] | R [B,1,1,8186]
// Structure: recompute-`a` phase 4, 24.6KB smem -> 8 CTAs/SM (max-MLP; robust
// to the elevated-latency host regime where the occ-5 variant collapses).
// New: phase 1 issues prefetch.global.L2 for the whole x2 row so phase-3
// x2 loads are L2 hits instead of DRAM-latency exposed.

namespace {
constexpr int L    = 4096;         // signal length
constexpr int NC   = 2051;         // dwt coeff count = (L+7)/2
constexpr int EXT  = L + 13;       // symmetric-extended length (4109)
constexpr int RLEN = 2 * L - 6;    // final idwt output length (8186)
constexpr int NV   = RLEN / 4 + 1; // 2047 quad-groups (last is a half group)

// REC_LO (analysis filter in the reference's conv — lax conv = cross-correlation)
__device__ constexpr float RLO[8] = {
     0.23037781330885523f,  0.7148465705525415f,   0.6308807679295904f,  -0.02798376941698385f,
    -0.18703481171888114f,  0.030841381835986965f, 0.032883011666982945f,-0.010597401784997278f};
// REC_HI[k] = (-1)^k * REC_LO[7-k]
__device__ constexpr float RHI[8] = {
    -0.010597401784997278f,-0.032883011666982945f, 0.030841381835986965f, 0.18703481171888114f,
    -0.02798376941698385f, -0.6308807679295904f,   0.7148465705525415f,  -0.23037781330885523f};
// DEC_LO[k] = REC_LO[7-k]
__device__ constexpr float DLO[8] = {
    -0.010597401784997278f, 0.032883011666982945f, 0.030841381835986965f,-0.18703481171888114f,
    -0.02798376941698385f,  0.6308807679295904f,   0.7148465705525415f,   0.23037781330885523f};
// DEC_HI[k] = REC_HI[7-k]
__device__ constexpr float DHI[8] = {
    -0.23037781330885523f,  0.7148465705525415f,  -0.6308807679295904f,  -0.02798376941698385f,
     0.18703481171888114f,  0.030841381835986965f,-0.032883011666982945f,-0.010597401784997278f};
} // namespace

__global__ __launch_bounds__(256, 8)
void wavelet_fused_kernel(const float* __restrict__ x1,
                          const float* __restrict__ x2,
                          float* __restrict__ out, int B)
{
    __shared__ alignas(16) float s_x[EXT + 3];   // ext(x1), then x2 row (first L)
    __shared__ alignas(16) float s_cD[NC + 5];   // +pad so tail reads stay in-bounds

    const int b = blockIdx.x;
    const int t = threadIdx.x;

    const float* __restrict__ x1row = x1 + (size_t)b * L;
    const float* __restrict__ x2row = x2 + (size_t)b * L;

    float* __restrict__ outA = out + (size_t)b * NC;
    float* __restrict__ outD = out + (size_t)B * NC + (size_t)b * (2 * L);
    float* __restrict__ outR = out + (size_t)B * NC + (size_t)B * (2 * L)
                                   + (size_t)b * RLEN;

    // ---- Phase 1: symmetric-extended x1 into smem; FILLER; x2 -> L2 prefetch ----
    // ext = [x5..x0 | x0..x_{L-1} | x_{L-1}..x_{L-7}]  (length L+13)
    if (t < 128)                                     // warm L2 with the x2 row
        asm volatile("prefetch.global.L2 [%0];" :: "l"(x2row + t * 32));
    for (int i4 = t; i4 < L / 4; i4 += 256) {        // body: float4 streaming loads
        float4 v = __ldcs(reinterpret_cast<const float4*>(x1row) + i4);
        int j = 6 + 4 * i4;
        s_x[j] = v.x; s_x[j + 1] = v.y; s_x[j + 2] = v.z; s_x[j + 3] = v.w;
    }
    if (t < 6)            s_x[t]     = __ldcs(x1row + 5 - t);      // head: x5..x0
    else if (t < 13)      s_x[L + t] = __ldcs(x1row + L + 5 - t);  // tail: x_{L-1}..x_{L-7}
    else if (t == 13) { s_cD[NC] = 0.f; s_cD[NC + 1] = 0.f; }      // cD pad
    for (int i = NC + t; i < L; i += 256) __stcs(outD + L + i, 10.1f);  // FILLER
    __syncthreads();

    // ---- Phase 2: DWT (stride-2, 8-tap), float2 smem reads ----
    {
        const float2* s_p = reinterpret_cast<const float2*>(s_x);
        for (int i = t; i < NC; i += 256) {
            float2 p0 = s_p[i], p1 = s_p[i + 1], p2 = s_p[i + 2], p3 = s_p[i + 3];
            float lo, hi;
            lo = fmaf(p0.x, RLO[0], p0.y * RLO[1]);
            lo = fmaf(p1.x, RLO[2], fmaf(p1.y, RLO[3], lo));
            lo = fmaf(p2.x, RLO[4], fmaf(p2.y, RLO[5], lo));
            lo = fmaf(p3.x, RLO[6], fmaf(p3.y, RLO[7], lo));
            hi = fmaf(p0.x, RHI[0], p0.y * RHI[1]);
            hi = fmaf(p1.x, RHI[2], fmaf(p1.y, RHI[3], hi));
            hi = fmaf(p2.x, RHI[4], fmaf(p2.y, RHI[5], hi));
            hi = fmaf(p3.x, RHI[6], fmaf(p3.y, RHI[7], hi));
            __stcs(outA + i, lo);
            s_cD[i] = hi;
            __stcs(outD + L + i, hi);        // cDs channel 1
        }
    }
    __syncthreads();

    // ---- Phase 3: overwrite s_x with x2 row (L2-warm); copy x2 -> cDs ch 0 ----
    for (int i4 = t; i4 < L / 4; i4 += 256) {
        float4 v = __ldcs(reinterpret_cast<const float4*>(x2row) + i4);
        reinterpret_cast<float4*>(s_x)[i4] = v;
        __stcs(reinterpret_cast<float4*>(outD) + i4, v);
    }
    __syncthreads();

    // ---- Phase 4: R = idwt(a, x2) with a = idwt(0, cD) recomputed on the fly ----
    // a[2v+s] are 4-tap combos of cD[v..v+5]; R quad (4v..4v+3) = pairs u=2v, 2v+1.
    // Even outputs use taps {1,3,5,7}, odd use {0,2,4,6}; no boundary clipping.
    for (int v = t; v < NV; v += 256) {
        float c0 = s_cD[v],     c1 = s_cD[v + 1], c2 = s_cD[v + 2];
        float c3 = s_cD[v + 3], c4 = s_cD[v + 4], c5 = s_cD[v + 5];

        float ae0 = fmaf(c0, DHI[1], fmaf(c1, DHI[3], fmaf(c2, DHI[5], c3 * DHI[7])));
        float ao0 = fmaf(c0, DHI[0], fmaf(c1, DHI[2], fmaf(c2, DHI[4], c3 * DHI[6])));
        float ae1 = fmaf(c1, DHI[1], fmaf(c2, DHI[3], fmaf(c3, DHI[5], c4 * DHI[7])));
        float ao1 = fmaf(c1, DHI[0], fmaf(c2, DHI[2], fmaf(c3, DHI[4], c4 * DHI[6])));

        float b0 = s_x[2 * v],     b1 = s_x[2 * v + 1], b2 = s_x[2 * v + 2];
        float b3 = s_x[2 * v + 3], b4 = s_x[2 * v + 4];

        // pair u = 2v  -> R[4v], R[4v+1]
        float e0 = fmaf(ae0, DLO[1], fmaf(ao0, DLO[3], fmaf(ae1, DLO[5], ao1 * DLO[7])));
        e0 = fmaf(b0, DHI[1], fmaf(b1, DHI[3], fmaf(b2, DHI[5], fmaf(b3, DHI[7], e0))));
        float o0 = fmaf(ae0, DLO[0], fmaf(ao0, DLO[2], fmaf(ae1, DLO[4], ao1 * DLO[6])));
        o0 = fmaf(b0, DHI[0], fmaf(b1, DHI[2], fmaf(b2, DHI[4], fmaf(b3, DHI[6], o0))));
        __stcs(reinterpret_cast<float2*>(outR + 4 * v), make_float2(e0, o0));

        if (v < NV - 1) {   // pair u = 2v+1 -> R[4v+2], R[4v+3] (absent in last group)
            float ae2 = fmaf(c2, DHI[1], fmaf(c3, DHI[3], fmaf(c4, DHI[5], c5 * DHI[7])));
            float e1 = fmaf(ao0, DLO[1], fmaf(ae1, DLO[3], fmaf(ao1, DLO[5], ae2 * DLO[7])));
            e1 = fmaf(b1, DHI[1], fmaf(b2, DHI[3], fmaf(b3, DHI[5], fmaf(b4, DHI[7], e1))));
            float o1 = fmaf(ao0, DLO[0], fmaf(ae1, DLO[2], fmaf(ao1, DLO[4], ae2 * DLO[6])));
            o1 = fmaf(b1, DHI[0], fmaf(b2, DHI[2], fmaf(b3, DHI[4], fmaf(b4, DHI[6], o1))));
            __stcs(reinterpret_cast<float2*>(outR + 4 * v + 2), make_float2(e1, o1));
        }
    }
}

extern "C" void kernel_launch(void* const* d_in, const int* in_sizes, int n_in,
                              void* d_out, int out_size) {
    const float* x1 = (const float*)d_in[0];   // [B,1,L]
    const float* x2 = (const float*)d_in[1];   // [B,1,1,L]
    // d_in[2] = x3 [B,1,1,1] is unused by the reference math.
    int B = in_sizes[2];                       // x3 has exactly B elements
    wavelet_fused_kernel<<<B, 256>>>(x1, x2, (float*)d_out, B);
}